// round 5
// baseline (speedup 1.0000x reference)
#include <cuda_runtime.h>
#include <math.h>

#define Bmax 1024
#define Nn   100
#define Hh   128
#define NHEADS 8
#define HD   16
#define NPAD 101
#define JKV  256
#define NEGV -1000000000.0f

// ---- device scratch (no cudaMalloc allowed) ----
__device__ float g_Wcat[Hh * 512];             // [k][j]: Wk^T | Wv^T | Wk2^T@Wo | Wqf[:, :128]^T
__device__ float g_Wqf [Hh * (Hh + 1)];        // Wq @ fc_w   (128 x 129)
__device__ float g_Wq1 [Hh * Hh];              // Wq @ fc1_w  (128 x 128)
__device__ float g_qpool[Bmax * Hh];           // (pool @ fc1_w^T) @ Wq^T
__device__ float g_EncProj[(size_t)Bmax * JKV * Nn];   // [b][j][n], j<256: K|V
__device__ float g_K2Wt[(size_t)Bmax * Nn * Hh];       // [b][n][j]  (K2@Wo) row-major
__device__ float g_QP  [(size_t)Bmax * Nn * Hh];       // [b][n][h]  enc @ Wqf[:, :128]^T

// =====================================================================
// Kernel 1: combine small weight matrices
// blocks 0..511 : column j of Wcat ; 512..639: Wqf rows ; 640..767: Wq1
// =====================================================================
__global__ void weights_kernel(const float* __restrict__ fc_w,
                               const float* __restrict__ fc1_w,
                               const float* __restrict__ Wq,
                               const float* __restrict__ Wk,
                               const float* __restrict__ Wv,
                               const float* __restrict__ Wo,
                               const float* __restrict__ Wk2)
{
    int bid = blockIdx.x, t = threadIdx.x;   // t = 0..127
    if (bid < 512) {
        int j = bid;
        float v;
        if (j < 128) {
            v = Wk[j * 128 + t];
        } else if (j < 256) {
            v = Wv[(j - 128) * 128 + t];
        } else if (j < 384) {
            int jp = j - 256;
            float s = 0.f;
            for (int h = 0; h < 128; h++) s += Wk2[h * 128 + t] * Wo[h * 128 + jp];
            v = s;
        } else {
            int hq = j - 384;          // Wqf[hq][t] = sum_jj Wq[hq][jj] * fc_w[jj][t]
            float s = 0.f;
            for (int jj = 0; jj < 128; jj++) s += Wq[hq * 128 + jj] * fc_w[jj * 129 + t];
            v = s;
        }
        g_Wcat[t * 512 + j] = v;
    } else if (bid < 640) {
        int i = bid - 512;
        for (int k = t; k < 129; k += 128) {
            float s = 0.f;
            for (int j = 0; j < 128; j++) s += Wq[i * 128 + j] * fc_w[j * 129 + k];
            g_Wqf[i * 129 + k] = s;
        }
    } else {
        int i = bid - 640;
        float s = 0.f;
        for (int j = 0; j < 128; j++) s += Wq[i * 128 + j] * fc1_w[j * 128 + t];
        g_Wq1[i * 128 + t] = s;
    }
}

// =====================================================================
// Kernel 2: qpool[b][h] = sum_k Wq1[h][k] * pool[b][k]
// =====================================================================
__global__ void qpool_kernel(const float* __restrict__ pool)
{
    int b = blockIdx.x, h = threadIdx.x;
    float s = 0.f;
    for (int k = 0; k < 128; k++) s += g_Wq1[h * 128 + k] * pool[b * 128 + k];
    g_qpool[b * 128 + h] = s;
}

// =====================================================================
// Kernel 3: projections. 512 threads; thread j owns weight column j.
// j<256  -> g_EncProj[b][j][n]      (K | V, n-contiguous)
// j<384  -> g_K2Wt[b][n][j-256]     (row-major, coalesced across threads)
// j<512  -> g_QP  [b][n][j-384]
// =====================================================================
__global__ __launch_bounds__(512, 1)
void encproj_kernel(const float* __restrict__ enc)
{
    extern __shared__ float As[];            // [100][128]
    int b = blockIdx.x, t = threadIdx.x;
    for (int i = t; i < Nn * Hh; i += 512) As[i] = enc[(size_t)b * Nn * Hh + i];
    float w[128];
#pragma unroll
    for (int k = 0; k < 128; k++) w[k] = g_Wcat[k * 512 + t];
    __syncthreads();

    float* rowp = (t < 256) ? (g_EncProj + (size_t)b * JKV * Nn + (size_t)t * Nn) : 0;
    float* colp = (t < 384) ? (g_K2Wt + (size_t)b * Nn * Hh + (t - 256))
                            : (g_QP   + (size_t)b * Nn * Hh + (t - 384));

    for (int n0 = 0; n0 < Nn; n0 += 4) {
        float a0 = 0.f, a1 = 0.f, a2 = 0.f, a3 = 0.f;
        const float4* r0 = reinterpret_cast<const float4*>(&As[(n0 + 0) * Hh]);
        const float4* r1 = reinterpret_cast<const float4*>(&As[(n0 + 1) * Hh]);
        const float4* r2 = reinterpret_cast<const float4*>(&As[(n0 + 2) * Hh]);
        const float4* r3 = reinterpret_cast<const float4*>(&As[(n0 + 3) * Hh]);
#pragma unroll
        for (int kk = 0; kk < 32; kk++) {
            float4 x0 = r0[kk];
            a0 += x0.x * w[4*kk] + x0.y * w[4*kk+1] + x0.z * w[4*kk+2] + x0.w * w[4*kk+3];
            float4 x1 = r1[kk];
            a1 += x1.x * w[4*kk] + x1.y * w[4*kk+1] + x1.z * w[4*kk+2] + x1.w * w[4*kk+3];
            float4 x2 = r2[kk];
            a2 += x2.x * w[4*kk] + x2.y * w[4*kk+1] + x2.z * w[4*kk+2] + x2.w * w[4*kk+3];
            float4 x3 = r3[kk];
            a3 += x3.x * w[4*kk] + x3.y * w[4*kk+1] + x3.z * w[4*kk+2] + x3.w * w[4*kk+3];
        }
        if (t < 256) {
            reinterpret_cast<float4*>(rowp + n0)[0] = make_float4(a0, a1, a2, a3);
        } else {
            colp[(size_t)(n0 + 0) * Hh] = a0;
            colp[(size_t)(n0 + 1) * Hh] = a1;
            colp[(size_t)(n0 + 2) * Hh] = a2;
            colp[(size_t)(n0 + 3) * Hh] = a3;
        }
    }
}

// =====================================================================
// Kernel 4: persistent per-batch decoder. 512 threads, 2 blocks/SM.
// smem: KT + VT only (~108 KB). K2W and QP read from global (L2).
// =====================================================================
#define DEC_SMEM_FLOATS (Hh*NPAD*2 + 128 + 128 + 128 + 800 + 128 + 104 + 104 + 104 + 8 + 8 + 104)
#define DEC_SMEM_BYTES  (DEC_SMEM_FLOATS * 4)

// rebuild active list (warp 0 only). act sorted ascending.
__device__ __forceinline__ void rebuild_active(int lane, int last_idx, float cap,
                                               const float* __restrict__ dem,
                                               const float* __restrict__ mask1,
                                               int* __restrict__ act, int* __restrict__ na_out)
{
    unsigned ball[4];
#pragma unroll
    for (int r = 0; r < 4; r++) {
        int n = r * 32 + lane;
        bool f = (n >= 1) && (n < Nn) && (mask1[n] == 0.f) && (dem[n] <= cap);
        ball[r] = __ballot_sync(0xffffffffu, f);
    }
    bool anyCust = (ball[0] | ball[1] | ball[2] | ball[3]) != 0u;
    bool depotA = (!anyCust) || (last_idx != 0);
    if (depotA) ball[0] |= 1u;
    int base = 0;
#pragma unroll
    for (int r = 0; r < 4; r++) {
        unsigned bl = ball[r];
        if ((bl >> lane) & 1u)
            act[base + __popc(bl & ((1u << lane) - 1u))] = r * 32 + lane;
        base += __popc(bl);
    }
    if (lane == 0) *na_out = base;
}

__global__ __launch_bounds__(512, 2)
void decode_kernel(const float* __restrict__ capacity,
                   const float* __restrict__ demand,
                   const int*   __restrict__ Tptr,
                   float* __restrict__ out, int ns, int B)
{
    extern __shared__ float sm[];
    float* KT    = sm;                    // 128*101 K^T [h'][n]
    float* VT    = KT   + Hh * NPAD;      // 128*101
    float* qp    = VT   + Hh * NPAD;      // 128 (qpool)
    float* wcap  = qp   + 128;            // 128 (Wqf[:,128])
    float* q     = wcap + 128;            // 128
    float* att   = q    + 128;            // 800
    float* g     = att  + 800;            // 128
    float* u     = g    + 128;            // 104
    float* dem   = u    + 104;            // 104
    float* mask1 = dem  + 104;            // 104
    float* misc  = mask1+ 104;            // 8: [0]=cap [1]=base [2]=logp [3]=invT
    int*   imisc = (int*)(misc + 8);      // [0]=idx [1]=visited [2]=na
    int*   act   = imisc + 8;             // 104

    const int b = blockIdx.x, t = threadIdx.x;
    const int w = t >> 5, lane = t & 31;
    const int h4 = t >> 2, p4 = t & 3;    // h4: 0..127, p4: 0..3

    // ---- load K,V (transposed, pad 101) ----
    const float* ep = g_EncProj + (size_t)b * JKV * Nn;
    for (int i = t; i < JKV * Nn; i += 512) {
        int j = i / Nn, n = i - j * Nn;
        sm[(j >> 7) * (Hh * NPAD) + (j & 127) * NPAD + n] = ep[i];
    }
    if (t < 128) {
        qp[t]   = g_qpool[b * 128 + t];
        wcap[t] = g_Wqf[t * 129 + 128];
    }
    if (t < Nn) { dem[t] = demand[b * Nn + t]; mask1[t] = 0.f; }
    if (t == 0) {
        float c = capacity[b];
        misc[0] = c; misc[1] = capacity[0]; misc[2] = 0.f;
        misc[3] = 1.0f / (float)(*Tptr);
        imisc[0] = 0; imisc[1] = 0;
    }
    __syncthreads();

    if (w == 0) rebuild_active(lane, 0, misc[0], dem, mask1, act, &imisc[2]);
    __syncthreads();

    const float* QPb  = g_QP   + (size_t)b * Nn * Hh;
    const float* K2b  = g_K2Wt + (size_t)b * Nn * Hh;

    for (int step = 0; step < ns; step++) {
        // ---- q[h] = QP[idx][h] + cap*wcap[h] + qpool[h] ----
        {
            int sidx = imisc[0];
            float capc = misc[0];
            if (t < 128)
                q[t] = qp[t] + QPb[(size_t)sidx * Hh + t] + capc * wcap[t];
        }
        __syncthreads();

        const int na = imisc[2];

        // ---- scores for active nodes ----
        for (int idx = t; idx < NHEADS * na; idx += 512) {
            int head = idx / na, i = idx - head * na;
            int n = act[i];
            const float* kp = KT + head * HD * NPAD + n;
            const float* qh = q + head * HD;
            float sc = 0.f;
#pragma unroll
            for (int d = 0; d < HD; d++) sc += qh[d] * kp[d * NPAD];
            att[head * Nn + i] = sc * 0.25f;
        }
        __syncthreads();

        // ---- softmax per head over na entries (warps 0..7) ----
        if (w < NHEADS) {
            float v[4], m = -3.4e38f;
#pragma unroll
            for (int r = 0; r < 4; r++) {
                int i = lane + 32 * r;
                v[r] = (i < na) ? att[w * Nn + i] : -3.4e38f;
                m = fmaxf(m, v[r]);
            }
#pragma unroll
            for (int off = 16; off; off >>= 1) m = fmaxf(m, __shfl_xor_sync(0xffffffffu, m, off));
            float e[4], ss = 0.f;
#pragma unroll
            for (int r = 0; r < 4; r++) {
                int i = lane + 32 * r;
                e[r] = (i < na) ? expf(v[r] - m) : 0.f;
                ss += e[r];
            }
#pragma unroll
            for (int off = 16; off; off >>= 1) ss += __shfl_xor_sync(0xffffffffu, ss, off);
            float inv = 1.f / ss;
#pragma unroll
            for (int r = 0; r < 4; r++) {
                int i = lane + 32 * r;
                if (i < na) att[w * Nn + i] = e[r] * inv;
            }
        }
        __syncthreads();

        // ---- g[h] = attn · V over active (4 partials/h via shfl) ----
        {
            const float* vp = VT + h4 * NPAD;
            const float* ap = att + (h4 >> 4) * Nn;
            float sg = 0.f;
            for (int i = p4; i < na; i += 4) sg += ap[i] * vp[act[i]];
            sg += __shfl_xor_sync(0xffffffffu, sg, 1);
            sg += __shfl_xor_sync(0xffffffffu, sg, 2);
            if (p4 == 0) g[h4] = sg;
        }
        __syncthreads();

        // ---- u[i] = CLIP*tanh(g · K2W[act[i]] / sqrt(H)) ; K2W from L2 ----
        // All threads run the shuffles (full mask); invalid lanes use row act[0].
        {
            const bool vi = (h4 < na);
            int n = vi ? act[h4] : act[0];
            const float4* kp = reinterpret_cast<const float4*>(K2b + (size_t)n * Hh + p4 * 32);
            const float4* gp = reinterpret_cast<const float4*>(g + p4 * 32);
            float su = 0.f;
#pragma unroll
            for (int rr = 0; rr < 8; rr++) {
                float4 kv = kp[rr];
                float4 gv = gp[rr];
                su += kv.x * gv.x + kv.y * gv.y + kv.z * gv.z + kv.w * gv.w;
            }
            su += __shfl_xor_sync(0xffffffffu, su, 1);
            su += __shfl_xor_sync(0xffffffffu, su, 2);
            if (p4 == 0 && vi) u[h4] = 10.f * tanhf(su * 0.08838834764831845f);
        }
        __syncthreads();

        // ---- argmax + log-softmax + state update + rebuild (warp 0) ----
        if (w == 0) {
            float invT = misc[3];
            float best = -3.4e38f; int bn = 0x7fffffff;
            float v[4];
#pragma unroll
            for (int r = 0; r < 4; r++) {
                int i = lane + 32 * r;
                if (i < na) {
                    float val = u[i] * invT;
                    int n = act[i]; v[r] = val;
                    if (val > best) { best = val; bn = n; }
                } else { v[r] = -3.4e38f; }
            }
#pragma unroll
            for (int off = 16; off; off >>= 1) {
                float ov = __shfl_xor_sync(0xffffffffu, best, off);
                int   on = __shfl_xor_sync(0xffffffffu, bn,   off);
                if (ov > best || (ov == best && on < bn)) { best = ov; bn = on; }
            }
            float ss = 0.f;
#pragma unroll
            for (int r = 0; r < 4; r++) {
                int i = lane + 32 * r;
                ss += (i < na) ? expf(v[r] - best) : 0.f;
            }
#pragma unroll
            for (int off = 16; off; off >>= 1) ss += __shfl_xor_sync(0xffffffffu, ss, off);

            if (lane == 0) {
                int idx = bn;
                imisc[0] = idx;
                if (imisc[1] < Nn - 1) misc[2] += -logf(ss);
                out[(size_t)b * ns + step] = (float)idx;
                float c = (idx == 0) ? misc[1] : misc[0] - dem[idx];
                misc[0] = c;
                if (idx > 0 && mask1[idx] == 0.f) { mask1[idx] = 1.f; imisc[1] += 1; }
            }
            __syncwarp();
            rebuild_active(lane, imisc[0], misc[0], dem, mask1, act, &imisc[2]);
        }
        __syncthreads();
    }

    if (t == 0) out[(size_t)B * ns + b] = misc[2];
}

// =====================================================================
// launch
// =====================================================================
extern "C" void kernel_launch(void* const* d_in, const int* in_sizes, int n_in,
                              void* d_out, int out_size)
{
    const float* enc      = (const float*)d_in[0];
    const float* pool     = (const float*)d_in[1];
    const float* capacity = (const float*)d_in[2];
    const float* demand   = (const float*)d_in[3];
    const float* fc_w     = (const float*)d_in[4];
    const float* fc1_w    = (const float*)d_in[5];
    const float* Wq       = (const float*)d_in[6];
    const float* Wk       = (const float*)d_in[7];
    const float* Wv       = (const float*)d_in[8];
    const float* Wo       = (const float*)d_in[9];
    const float* Wk2      = (const float*)d_in[10];
    const int*   Tptr     = (const int*)d_in[12];

    int B  = in_sizes[0] / (Nn * Hh);          // 1024
    int ns = out_size / B - 1;                 // 128
    float* out = (float*)d_out;

    weights_kernel<<<768, 128>>>(fc_w, fc1_w, Wq, Wk, Wv, Wo, Wk2);
    qpool_kernel<<<B, 128>>>(pool);

    cudaFuncSetAttribute(encproj_kernel, cudaFuncAttributeMaxDynamicSharedMemorySize, Nn * Hh * 4);
    encproj_kernel<<<B, 512, Nn * Hh * 4>>>(enc);

    cudaFuncSetAttribute(decode_kernel, cudaFuncAttributeMaxDynamicSharedMemorySize, DEC_SMEM_BYTES);
    decode_kernel<<<B, 512, DEC_SMEM_BYTES>>>(capacity, demand, Tptr, out, ns, B);
}

// round 7
// speedup vs baseline: 1.3261x; 1.3261x over previous
#include <cuda_runtime.h>
#include <math.h>

#define Bmax 1024
#define Nn   100
#define Hh   128
#define NHEADS 8
#define HD   16
#define NPAD 101
#define JALL 384
#define NEGV -1000000000.0f

// ---- device scratch (no cudaMalloc allowed) ----
__device__ float g_Wcat[Hh * 512];             // [k][j]: Wk^T | Wv^T | Wk2^T@Wo | Wqf[:, :128]^T
__device__ float g_Wqf [Hh * (Hh + 1)];        // Wq @ fc_w   (128 x 129)
__device__ float g_Wq1 [Hh * Hh];              // Wq @ fc1_w  (128 x 128)
__device__ float g_qpool[Bmax * Hh];           // (pool @ fc1_w^T) @ Wq^T
__device__ float g_EncProj[(size_t)Bmax * JALL * Nn];  // [b][j][n]: K | V | K2W
__device__ float g_QP  [(size_t)Bmax * Nn * Hh];       // [b][n][h]  enc @ Wqf[:, :128]^T

// =====================================================================
// Kernel 1: combine small weight matrices
// =====================================================================
__global__ void weights_kernel(const float* __restrict__ fc_w,
                               const float* __restrict__ fc1_w,
                               const float* __restrict__ Wq,
                               const float* __restrict__ Wk,
                               const float* __restrict__ Wv,
                               const float* __restrict__ Wo,
                               const float* __restrict__ Wk2)
{
    int bid = blockIdx.x, t = threadIdx.x;   // t = 0..127
    if (bid < 512) {
        int j = bid;
        float v;
        if (j < 128) {
            v = Wk[j * 128 + t];
        } else if (j < 256) {
            v = Wv[(j - 128) * 128 + t];
        } else if (j < 384) {
            int jp = j - 256;
            float s = 0.f;
            for (int h = 0; h < 128; h++) s += Wk2[h * 128 + t] * Wo[h * 128 + jp];
            v = s;
        } else {
            int hq = j - 384;          // Wqf[hq][t]
            float s = 0.f;
            for (int jj = 0; jj < 128; jj++) s += Wq[hq * 128 + jj] * fc_w[jj * 129 + t];
            v = s;
        }
        g_Wcat[t * 512 + j] = v;
    } else if (bid < 640) {
        int i = bid - 512;
        for (int k = t; k < 129; k += 128) {
            float s = 0.f;
            for (int j = 0; j < 128; j++) s += Wq[i * 128 + j] * fc_w[j * 129 + k];
            g_Wqf[i * 129 + k] = s;
        }
    } else {
        int i = bid - 640;
        float s = 0.f;
        for (int j = 0; j < 128; j++) s += Wq[i * 128 + j] * fc1_w[j * 128 + t];
        g_Wq1[i * 128 + t] = s;
    }
}

// =====================================================================
// Kernel 2: qpool[b][h] = sum_k Wq1[h][k] * pool[b][k]
// =====================================================================
__global__ void qpool_kernel(const float* __restrict__ pool)
{
    int b = blockIdx.x, h = threadIdx.x;
    float s = 0.f;
    for (int k = 0; k < 128; k++) s += g_Wq1[h * 128 + k] * pool[b * 128 + k];
    g_qpool[b * 128 + h] = s;
}

// =====================================================================
// Kernel 3: projections. 512 threads; thread j owns weight column j.
// j<384  -> g_EncProj[b][j][n]   (K | V | K2W, n-contiguous)
// j<512  -> g_QP[b][n][j-384]    (row-major, coalesced across threads)
// =====================================================================
__global__ __launch_bounds__(512, 1)
void encproj_kernel(const float* __restrict__ enc)
{
    extern __shared__ float As[];            // [100][128]
    int b = blockIdx.x, t = threadIdx.x;
    for (int i = t; i < Nn * Hh; i += 512) As[i] = enc[(size_t)b * Nn * Hh + i];
    float w[128];
#pragma unroll
    for (int k = 0; k < 128; k++) w[k] = g_Wcat[k * 512 + t];
    __syncthreads();

    float* rowp = (t < 384) ? (g_EncProj + (size_t)b * JALL * Nn + (size_t)t * Nn) : 0;
    float* colp = g_QP + (size_t)b * Nn * Hh + (t - 384);

    for (int n0 = 0; n0 < Nn; n0 += 4) {
        float a0 = 0.f, a1 = 0.f, a2 = 0.f, a3 = 0.f;
        const float4* r0 = reinterpret_cast<const float4*>(&As[(n0 + 0) * Hh]);
        const float4* r1 = reinterpret_cast<const float4*>(&As[(n0 + 1) * Hh]);
        const float4* r2 = reinterpret_cast<const float4*>(&As[(n0 + 2) * Hh]);
        const float4* r3 = reinterpret_cast<const float4*>(&As[(n0 + 3) * Hh]);
#pragma unroll
        for (int kk = 0; kk < 32; kk++) {
            float4 x0 = r0[kk];
            a0 += x0.x * w[4*kk] + x0.y * w[4*kk+1] + x0.z * w[4*kk+2] + x0.w * w[4*kk+3];
            float4 x1 = r1[kk];
            a1 += x1.x * w[4*kk] + x1.y * w[4*kk+1] + x1.z * w[4*kk+2] + x1.w * w[4*kk+3];
            float4 x2 = r2[kk];
            a2 += x2.x * w[4*kk] + x2.y * w[4*kk+1] + x2.z * w[4*kk+2] + x2.w * w[4*kk+3];
            float4 x3 = r3[kk];
            a3 += x3.x * w[4*kk] + x3.y * w[4*kk+1] + x3.z * w[4*kk+2] + x3.w * w[4*kk+3];
        }
        if (t < 384) {
            reinterpret_cast<float4*>(rowp + n0)[0] = make_float4(a0, a1, a2, a3);
        } else {
            colp[(size_t)(n0 + 0) * Hh] = a0;
            colp[(size_t)(n0 + 1) * Hh] = a1;
            colp[(size_t)(n0 + 2) * Hh] = a2;
            colp[(size_t)(n0 + 3) * Hh] = a3;
        }
    }
}

// =====================================================================
// Kernel 4: persistent per-batch decoder. 512 threads, 1 block/SM.
// All operands in smem (KT,VT,K2T,QP). 4 barriers/step.
// =====================================================================
#define DEC_SMEM_FLOATS (Hh*NPAD*3 + Nn*Hh + 128 + 128 + 800 + 128 + 104 + 104 + 104 + 8 + 8 + 104)
#define DEC_SMEM_BYTES  (DEC_SMEM_FLOATS * 4)

// rebuild active list (warp 0 only). act sorted ascending.
__device__ __forceinline__ void rebuild_active(int lane, int last_idx, float cap,
                                               const float* __restrict__ dem,
                                               const float* __restrict__ mask1,
                                               int* __restrict__ act, int* __restrict__ na_out)
{
    unsigned ball[4];
#pragma unroll
    for (int r = 0; r < 4; r++) {
        int n = r * 32 + lane;
        bool f = (n >= 1) && (n < Nn) && (mask1[n] == 0.f) && (dem[n] <= cap);
        ball[r] = __ballot_sync(0xffffffffu, f);
    }
    bool anyCust = (ball[0] | ball[1] | ball[2] | ball[3]) != 0u;
    bool depotA = (!anyCust) || (last_idx != 0);
    if (depotA) ball[0] |= 1u;
    int base = 0;
#pragma unroll
    for (int r = 0; r < 4; r++) {
        unsigned bl = ball[r];
        if ((bl >> lane) & 1u)
            act[base + __popc(bl & ((1u << lane) - 1u))] = r * 32 + lane;
        base += __popc(bl);
    }
    if (lane == 0) *na_out = base;
}

__global__ __launch_bounds__(512, 1)
void decode_kernel(const float* __restrict__ capacity,
                   const float* __restrict__ demand,
                   const int*   __restrict__ Tptr,
                   float* __restrict__ out, int ns, int B)
{
    extern __shared__ float sm[];
    float* KT    = sm;                    // 128*101 K^T  [h'][n]
    float* VT    = KT   + Hh * NPAD;      // 128*101 V^T
    float* K2T   = VT   + Hh * NPAD;      // 128*101 (K2@Wo)^T
    float* QPs   = K2T  + Hh * NPAD;      // 100*128 [n][h]
    float* qp    = QPs  + Nn * Hh;        // 128 (qpool)
    float* wcap  = qp   + 128;            // 128 (Wqf[:,128])
    float* att   = wcap + 128;            // 800
    float* g     = att  + 800;            // 128
    float* u     = g    + 128;            // 104
    float* dem   = u    + 104;            // 104
    float* mask1 = dem  + 104;            // 104
    float* misc  = mask1+ 104;            // 8: [0]=cap [1]=base [2]=logp [3]=invT
    int*   imisc = (int*)(misc + 8);      // [0]=idx [1]=visited [2]=na
    int*   act   = imisc + 8;             // 104

    const int b = blockIdx.x, t = threadIdx.x;
    const int w = t >> 5, lane = t & 31;
    const int h4 = t >> 2, p4 = t & 3;    // h4: 0..127, p4: 0..3

    // ---- load K,V,K2W (transposed, pad 101) + QP ----
    const float* ep = g_EncProj + (size_t)b * JALL * Nn;
    for (int i = t; i < JALL * Nn; i += 512) {
        int j = i / Nn, n = i - j * Nn;
        sm[(j >> 7) * (Hh * NPAD) + (j & 127) * NPAD + n] = ep[i];
    }
    const float* qpg = g_QP + (size_t)b * Nn * Hh;
    for (int i = t; i < Nn * Hh; i += 512) QPs[i] = qpg[i];
    if (t < 128) {
        qp[t]   = g_qpool[b * 128 + t];
        wcap[t] = g_Wqf[t * 129 + 128];
    }
    if (t < Nn) { dem[t] = demand[b * Nn + t]; mask1[t] = 0.f; }
    if (t == 0) {
        float c = capacity[b];
        misc[0] = c; misc[1] = capacity[0]; misc[2] = 0.f;
        misc[3] = 1.0f / (float)(*Tptr);
        imisc[0] = 0; imisc[1] = 0;
    }
    __syncthreads();

    if (w == 0) rebuild_active(lane, 0, misc[0], dem, mask1, act, &imisc[2]);
    __syncthreads();

    for (int step = 0; step < ns; step++) {
        const int na = imisc[2];

        // ==== R1: scores + softmax, warp w = head w (warps 0..7) ====
        if (w < NHEADS) {
            // per-warp q chunk: lane d<16 computes q[16w+d]
            int sidx = imisc[0];
            float capc = misc[0];
            float qd = 0.f;
            if (lane < HD) {
                int hh = w * HD + lane;
                qd = qp[hh] + QPs[sidx * Hh + hh] + capc * wcap[hh];
            }
            // scores: lane covers i, i+32, i+64, i+96
            int i0 = lane, i1 = lane + 32, i2 = lane + 64, i3 = lane + 96;
            int n0 = (i0 < na) ? act[i0] : act[0];
            int n1 = (i1 < na) ? act[i1] : act[0];
            int n2 = (i2 < na) ? act[i2] : act[0];
            int n3 = (i3 < na) ? act[i3] : act[0];
            const float* kb = KT + w * HD * NPAD;
            float s0 = 0.f, s1 = 0.f, s2 = 0.f, s3 = 0.f;
#pragma unroll
            for (int d = 0; d < HD; d++) {
                float qv = __shfl_sync(0xffffffffu, qd, d);
                const float* kr = kb + d * NPAD;
                s0 += qv * kr[n0];
                s1 += qv * kr[n1];
                s2 += qv * kr[n2];
                s3 += qv * kr[n3];
            }
            float v0 = (i0 < na) ? s0 * 0.25f : -3.4e38f;
            float v1 = (i1 < na) ? s1 * 0.25f : -3.4e38f;
            float v2 = (i2 < na) ? s2 * 0.25f : -3.4e38f;
            float v3 = (i3 < na) ? s3 * 0.25f : -3.4e38f;
            // warp softmax over na entries
            float m = fmaxf(fmaxf(v0, v1), fmaxf(v2, v3));
#pragma unroll
            for (int off = 16; off; off >>= 1) m = fmaxf(m, __shfl_xor_sync(0xffffffffu, m, off));
            float e0 = (i0 < na) ? expf(v0 - m) : 0.f;
            float e1 = (i1 < na) ? expf(v1 - m) : 0.f;
            float e2 = (i2 < na) ? expf(v2 - m) : 0.f;
            float e3 = (i3 < na) ? expf(v3 - m) : 0.f;
            float ss = e0 + e1 + e2 + e3;
#pragma unroll
            for (int off = 16; off; off >>= 1) ss += __shfl_xor_sync(0xffffffffu, ss, off);
            float inv = 1.f / ss;
            if (i0 < na) att[w * Nn + i0] = e0 * inv;
            if (i1 < na) att[w * Nn + i1] = e1 * inv;
            if (i2 < na) att[w * Nn + i2] = e2 * inv;
            if (i3 < na) att[w * Nn + i3] = e3 * inv;
        }
        __syncthreads();

        // ==== R2: g[h] = attn · V over active (4 partials/h via shfl) ====
        {
            const float* vp = VT + h4 * NPAD;
            const float* ap = att + (h4 >> 4) * Nn;
            float sg = 0.f;
            for (int i = p4; i < na; i += 4) sg += ap[i] * vp[act[i]];
            sg += __shfl_xor_sync(0xffffffffu, sg, 1);
            sg += __shfl_xor_sync(0xffffffffu, sg, 2);
            if (p4 == 0) g[h4] = sg;
        }
        __syncthreads();

        // ==== R3: u[i] = CLIP*tanh(g · K2T[:,act[i]] / sqrt(H)) ====
        {
            const bool vi = (h4 < na);
            const float* kp = K2T + (vi ? act[h4] : act[0]);
            float su = 0.f;
#pragma unroll
            for (int rr = 0; rr < 32; rr++) {
                int j = p4 * 32 + ((rr + p4 * 8) & 31);
                su += g[j] * kp[j * NPAD];
            }
            su += __shfl_xor_sync(0xffffffffu, su, 1);
            su += __shfl_xor_sync(0xffffffffu, su, 2);
            if (p4 == 0 && vi) u[h4] = 10.f * tanhf(su * 0.08838834764831845f);
        }
        __syncthreads();

        // ==== R4: argmax + log-softmax + state update + rebuild (warp 0) ====
        if (w == 0) {
            float invT = misc[3];
            float best = -3.4e38f; int bn = 0x7fffffff;
            float v[4];
#pragma unroll
            for (int r = 0; r < 4; r++) {
                int i = lane + 32 * r;
                if (i < na) {
                    float val = u[i] * invT;
                    int n = act[i]; v[r] = val;
                    if (val > best) { best = val; bn = n; }
                } else { v[r] = -3.4e38f; }
            }
#pragma unroll
            for (int off = 16; off; off >>= 1) {
                float ov = __shfl_xor_sync(0xffffffffu, best, off);
                int   on = __shfl_xor_sync(0xffffffffu, bn,   off);
                if (ov > best || (ov == best && on < bn)) { best = ov; bn = on; }
            }
            float ss = 0.f;
#pragma unroll
            for (int r = 0; r < 4; r++) {
                int i = lane + 32 * r;
                ss += (i < na) ? expf(v[r] - best) : 0.f;
            }
#pragma unroll
            for (int off = 16; off; off >>= 1) ss += __shfl_xor_sync(0xffffffffu, ss, off);

            if (lane == 0) {
                int idx = bn;
                imisc[0] = idx;
                if (imisc[1] < Nn - 1) misc[2] += -logf(ss);
                out[(size_t)b * ns + step] = (float)idx;
                float c = (idx == 0) ? misc[1] : misc[0] - dem[idx];
                misc[0] = c;
                if (idx > 0 && mask1[idx] == 0.f) { mask1[idx] = 1.f; imisc[1] += 1; }
            }
            __syncwarp();
            rebuild_active(lane, imisc[0], misc[0], dem, mask1, act, &imisc[2]);
        }
        __syncthreads();
    }

    if (t == 0) out[(size_t)B * ns + b] = misc[2];
}

// =====================================================================
// launch
// =====================================================================
extern "C" void kernel_launch(void* const* d_in, const int* in_sizes, int n_in,
                              void* d_out, int out_size)
{
    const float* enc      = (const float*)d_in[0];
    const float* pool     = (const float*)d_in[1];
    const float* capacity = (const float*)d_in[2];
    const float* demand   = (const float*)d_in[3];
    const float* fc_w     = (const float*)d_in[4];
    const float* fc1_w    = (const float*)d_in[5];
    const float* Wq       = (const float*)d_in[6];
    const float* Wk       = (const float*)d_in[7];
    const float* Wv       = (const float*)d_in[8];
    const float* Wo       = (const float*)d_in[9];
    const float* Wk2      = (const float*)d_in[10];
    const int*   Tptr     = (const int*)d_in[12];

    int B  = in_sizes[0] / (Nn * Hh);          // 1024
    int ns = out_size / B - 1;                 // 128
    float* out = (float*)d_out;

    weights_kernel<<<768, 128>>>(fc_w, fc1_w, Wq, Wk, Wv, Wo, Wk2);
    qpool_kernel<<<B, 128>>>(pool);

    cudaFuncSetAttribute(encproj_kernel, cudaFuncAttributeMaxDynamicSharedMemorySize, Nn * Hh * 4);
    encproj_kernel<<<B, 512, Nn * Hh * 4>>>(enc);

    cudaFuncSetAttribute(decode_kernel, cudaFuncAttributeMaxDynamicSharedMemorySize, DEC_SMEM_BYTES);
    decode_kernel<<<B, 512, DEC_SMEM_BYTES>>>(capacity, demand, Tptr, out, ns, B);
}